// round 13
// baseline (speedup 1.0000x reference)
#include <cuda_runtime.h>
#include <cstdint>

// Kuramoto oscillators: B=32, N=2048, K=8, T=20.
// R13: R12's warp-specialized batch pairing at FULL grid. 16 clusters x 8
// CTAs (grid=128), 512 threads/CTA. Threads 0-255 run batch 0, threads
// 256-511 run batch 1 (one thread per oscillator per batch, 256 osc/CTA).
// Halves sync independently (named barriers bar.sync 1/2,256 + per-batch
// mbarriers), so one half's DSMEM exchange round-trip hides behind the other
// half's compute. Exchange per half = validated push: STS slice -> named bar
// -> 7 lead threads fence + cp.async.bulk 1KB to each peer with complete_tx
// on the peer's per-batch per-buffer mbarrier (expect 7KB, acquire.cta wait,
// early arming; transient-negative tx legal).
// Duplicate scatter targets: LAST k wins; n = #distinct nonzero targets.
// eps/n folded into the weights (eps=1, anneal=0).

#define Nn 2048
#define Kk 8
#define Bb 32
#define Tt 20
#define CSZ 8
#define JB 2                                   // batches per cluster
#define THREADS 512                            // 256 per batch-half
#define HALF 256
#define NPC (Nn / CSZ)                         // 256 oscillators per CTA/batch
#define SLICE_BYTES (NPC * 4)                  // 1024 bytes per push
#define EXPECT_BYTES ((CSZ - 1) * SLICE_BYTES) // 7168 remote bytes per step

#define TWO_PI     6.28318530717958647692f
#define INV_TWO_PI 0.15915494309189533577f

__device__ __forceinline__ uint32_t smem_u32(const void* p) {
    uint32_t a;
    asm("{ .reg .u64 t; cvta.to.shared.u64 t, %1; cvt.u32.u64 %0, t; }"
        : "=r"(a) : "l"(p));
    return a;
}

__device__ __forceinline__ uint32_t mapa_u32(uint32_t laddr, uint32_t rank) {
    uint32_t r;
    asm("mapa.shared::cluster.u32 %0, %1, %2;" : "=r"(r) : "r"(laddr), "r"(rank));
    return r;
}

__device__ __forceinline__ void mbar_init(uint32_t laddr, uint32_t count) {
    asm volatile("mbarrier.init.shared.b64 [%0], %1;" :: "r"(laddr), "r"(count) : "memory");
}

__device__ __forceinline__ void mbar_arrive_expect_tx(uint32_t laddr, uint32_t tx) {
    asm volatile("mbarrier.arrive.expect_tx.shared.b64 _, [%0], %1;"
                 :: "r"(laddr), "r"(tx) : "memory");
}

__device__ __forceinline__ void bulk_s2s_cluster(uint32_t dst_cluster,
                                                 uint32_t src_cta,
                                                 uint32_t bytes,
                                                 uint32_t rmbar_cluster) {
    asm volatile(
        "cp.async.bulk.shared::cluster.shared::cta.mbarrier::complete_tx::bytes "
        "[%0], [%1], %2, [%3];"
        :: "r"(dst_cluster), "r"(src_cta), "r"(bytes), "r"(rmbar_cluster)
        : "memory");
}

// CTA-scope acquire wait (validated R8/R10/R12)
__device__ __forceinline__ void mbar_wait(uint32_t laddr, uint32_t parity) {
    uint32_t done;
    asm volatile(
        "{ .reg .pred p;\n"
        "  mbarrier.try_wait.parity.acquire.cta.shared::cta.b64 p, [%1], %2;\n"
        "  selp.b32 %0, 1, 0, p; }"
        : "=r"(done) : "r"(laddr), "r"(parity) : "memory");
    if (!done) {
        asm volatile(
            "{ .reg .pred p;\n"
            "WL_%=:\n"
            "  mbarrier.try_wait.parity.acquire.cta.shared::cta.b64 p, [%0], %1, 0x989680;\n"
            "  @p bra.uni WD_%=;\n"
            "  bra.uni WL_%=;\n"
            "WD_%=: }"
            :: "r"(laddr), "r"(parity) : "memory");
    }
}

__global__ void __launch_bounds__(THREADS, 1) __cluster_dims__(CSZ, 1, 1)
osc_kernel(const float* __restrict__ coupling,   // [B,N,K]
           const float* __restrict__ phase0,     // [B,N]
           const float* __restrict__ omega,      // [B,N]
           const int*   __restrict__ conn,       // [N,K]
           float*       __restrict__ out)        // [T+1,B,N]
{
    __shared__ __align__(16) float th[JB][2][Nn];           // per-batch replicas
    __shared__ __align__(8)  unsigned long long mbar[JB][2];

    uint32_t rank;
    asm("mov.u32 %0, %%cluster_ctarank;" : "=r"(rank));
    const int cid = blockIdx.x / CSZ;            // cluster id 0..15
    const int tid = threadIdx.x;
    const int j   = tid >> 8;                    // batch half: 0 or 1
    const int lt  = tid & (HALF - 1);            // thread id within half
    const int n   = (int)rank * NPC + lt;        // this thread's oscillator
    const int bj  = cid * JB + j;                // global batch element
    const uint32_t barid = 1u + (uint32_t)j;     // named barrier per half

    const uint32_t mb_l[2] = { smem_u32(&mbar[j][0]), smem_u32(&mbar[j][1]) };
    if (tid == 0) {
        mbar_init(smem_u32(&mbar[0][0]), 1);
        mbar_init(smem_u32(&mbar[0][1]), 1);
        mbar_init(smem_u32(&mbar[1][0]), 1);
        mbar_init(smem_u32(&mbar[1][1]), 1);
    }

    // ---- prologue: dedup couplings, fold eps/n into weights ----
    float w[Kk];
    int   off[Kk];
    int idx[Kk];
    #pragma unroll
    for (int k = 0; k < Kk; ++k) idx[k] = conn[n * Kk + k];

    int cnt = 0;
    #pragma unroll
    for (int k = 0; k < Kk; ++k) {
        bool win = true;
        #pragma unroll
        for (int k2 = k + 1; k2 < Kk; ++k2) win = win && (idx[k2] != idx[k]);
        const float c = coupling[((size_t)bj * Nn + n) * Kk + k];
        w[k]   = win ? c : 0.0f;
        off[k] = idx[k];
        cnt += (win && (c != 0.0f)) ? 1 : 0;
    }
    const float inv = (cnt > 0) ? (1.0f / (float)cnt) : 0.0f;
    #pragma unroll
    for (int k = 0; k < Kk; ++k) w[k] *= inv;

    float p  = phase0[(size_t)bj * Nn + n];
    const float om = omega[(size_t)bj * Nn + n];
    out[(size_t)bj * Nn + n] = p;                // t=0 slice

    // each half fills its batch's FULL replica from gmem (8 per thread)
    #pragma unroll
    for (int q = 0; q < CSZ; ++q) {
        const int m  = lt + q * HALF;
        const float ph = phase0[(size_t)bj * Nn + m];
        th[j][0][m] = ph - TWO_PI * rintf(ph * INV_TWO_PI);
    }
    float pr = p - TWO_PI * rintf(p * INV_TWO_PI);

    // hoisted push addresses (lead threads lt<7 of each half)
    const uint32_t peer = (lt < CSZ - 1)
        ? ((uint32_t)lt < rank ? (uint32_t)lt : (uint32_t)(lt + 1)) : 0u;
    const uint32_t src_l[2] = { smem_u32(&th[j][0][rank * NPC]),
                                smem_u32(&th[j][1][rank * NPC]) };
    uint32_t dst_r[2], mbr_r[2];
    if (lt < CSZ - 1) {
        dst_r[0] = mapa_u32(src_l[0], peer);
        dst_r[1] = mapa_u32(src_l[1], peer);
        mbr_r[0] = mapa_u32(mb_l[0], peer);
        mbr_r[1] = mapa_u32(mb_l[1], peer);
    }

    __syncthreads();   // replicas + mbarrier init complete at CTA scope
    // cluster-wide: all mbarriers initialized before any peer bulk signals
    asm volatile("barrier.cluster.arrive.aligned;" ::: "memory");
    asm volatile("barrier.cluster.wait.aligned;"   ::: "memory");

    uint32_t par[2] = {0, 0};

    // ---- time stepping (each half runs independently) ----
    #pragma unroll 1
    for (int t = 0; t < Tt; ++t) {
        const int c  = t & 1;
        const int nb = c ^ 1;

        if (t > 0) {                 // this batch's 7KB of buffer c arrived
            mbar_wait(mb_l[c], par[c]);
            par[c] ^= 1u;
        }
        // arm next buffer's barrier early (transient-negative tx is legal)
        if (t < Tt - 1 && lt == 0)
            mbar_arrive_expect_tx(mb_l[nb], EXPECT_BYTES);

        const float* __restrict__ cur = th[j][c];

        float acc = 0.0f;
        #pragma unroll
        for (int k = 0; k < Kk; ++k)
            acc += w[k] * __sinf(cur[off[k]] - pr);   // arg in [-2pi, 2pi]

        p += acc + om;
        const float prn = p - TWO_PI * rintf(p * INV_TWO_PI);
        pr = prn;

        // own slice + global output
        th[j][nb][n] = prn;
        out[(size_t)(t + 1) * (Bb * Nn) + (size_t)bj * Nn + n] = p;

        if (t < Tt - 1) {
            // per-half barrier: drains this half's STS; other half's warps
            // keep the SM busy during our exchange round-trip
            asm volatile("bar.sync %0, %1;" :: "r"(barid), "r"((uint32_t)HALF)
                         : "memory");
            if (lt < CSZ - 1) {
                asm volatile("fence.proxy.async.shared::cta;" ::: "memory");
                bulk_s2s_cluster(dst_r[nb], src_l[nb], SLICE_BYTES, mbr_r[nb]);
            }
        }
    }
}

extern "C" void kernel_launch(void* const* d_in, const int* in_sizes, int n_in,
                              void* d_out, int out_size)
{
    const float* coupling = (const float*)d_in[0];   // [B,N,K] f32
    const float* phase0   = (const float*)d_in[1];   // [B,N]   f32
    const float* omega    = (const float*)d_in[2];   // [B,N]   f32
    const int*   conn     = (const int*)  d_in[3];   // [N,K]   i32
    float*       out      = (float*)d_out;           // [T+1,B,N] f32

    osc_kernel<<<(Bb / JB) * CSZ, THREADS>>>(coupling, phase0, omega, conn, out);
}

// round 14
// speedup vs baseline: 1.1843x; 1.1843x over previous
#include <cuda_runtime.h>
#include <cstdint>

// Kuramoto oscillators: B=32, N=2048, K=8, T=20.
// R14: R4 (best, 21.2us) with the send->wait gap filled. 32 clusters x 4 CTAs
// (grid=128), 512 thr/CTA, 1 osc/thread. Per step:
//   wait(buf c) -> prefetch 8 neighbor LDS -> 8x __sinf -> update
//   -> STS own slice into th[nb] -> __syncthreads
//   -> 3 lead threads: fence + cp.async.bulk 2KB to each peer (complete_tx)
//   -> STG output + arm mb[nb]   (both in the gap, off the critical path)
// Waits are acquire.cta try_wait (validated R8+). Transient-negative tx on
// the armed-late barrier is legal (validated R4+).
// Duplicate scatter targets: LAST k wins; n = #distinct nonzero targets.
// eps/n folded into the weights (eps=1, anneal=0).

#define Nn 2048
#define Kk 8
#define Bb 32
#define Tt 20
#define CSZ 4
#define THREADS 512
#define NPC (Nn / CSZ)                          // 512 oscillators per CTA
#define SLICE_BYTES (NPC * 4)                   // 2048 bytes per push
#define EXPECT_BYTES ((CSZ - 1) * SLICE_BYTES)  // 6144 remote bytes per step

#define TWO_PI     6.28318530717958647692f
#define INV_TWO_PI 0.15915494309189533577f

__device__ __forceinline__ uint32_t smem_u32(const void* p) {
    uint32_t a;
    asm("{ .reg .u64 t; cvta.to.shared.u64 t, %1; cvt.u32.u64 %0, t; }"
        : "=r"(a) : "l"(p));
    return a;
}

__device__ __forceinline__ uint32_t mapa_u32(uint32_t laddr, uint32_t rank) {
    uint32_t r;
    asm("mapa.shared::cluster.u32 %0, %1, %2;" : "=r"(r) : "r"(laddr), "r"(rank));
    return r;
}

__device__ __forceinline__ void mbar_init(uint32_t laddr, uint32_t count) {
    asm volatile("mbarrier.init.shared.b64 [%0], %1;" :: "r"(laddr), "r"(count) : "memory");
}

__device__ __forceinline__ void mbar_arrive_expect_tx(uint32_t laddr, uint32_t tx) {
    asm volatile("mbarrier.arrive.expect_tx.shared.b64 _, [%0], %1;"
                 :: "r"(laddr), "r"(tx) : "memory");
}

__device__ __forceinline__ void bulk_s2s_cluster(uint32_t dst_cluster,
                                                 uint32_t src_cta,
                                                 uint32_t bytes,
                                                 uint32_t rmbar_cluster) {
    asm volatile(
        "cp.async.bulk.shared::cluster.shared::cta.mbarrier::complete_tx::bytes "
        "[%0], [%1], %2, [%3];"
        :: "r"(dst_cluster), "r"(src_cta), "r"(bytes), "r"(rmbar_cluster)
        : "memory");
}

// CTA-scope acquire wait (validated R8/R10/R12/R13)
__device__ __forceinline__ void mbar_wait(uint32_t laddr, uint32_t parity) {
    uint32_t done;
    asm volatile(
        "{ .reg .pred p;\n"
        "  mbarrier.try_wait.parity.acquire.cta.shared::cta.b64 p, [%1], %2, 0x989680;\n"
        "  selp.b32 %0, 1, 0, p; }"
        : "=r"(done) : "r"(laddr), "r"(parity) : "memory");
    if (!done) {
        asm volatile(
            "{ .reg .pred p;\n"
            "WL_%=:\n"
            "  mbarrier.try_wait.parity.acquire.cta.shared::cta.b64 p, [%0], %1, 0x989680;\n"
            "  @p bra.uni WD_%=;\n"
            "  bra.uni WL_%=;\n"
            "WD_%=: }"
            :: "r"(laddr), "r"(parity) : "memory");
    }
}

__global__ void __launch_bounds__(THREADS, 1) __cluster_dims__(CSZ, 1, 1)
osc_kernel(const float* __restrict__ coupling,   // [B,N,K]
           const float* __restrict__ phase0,     // [B,N]
           const float* __restrict__ omega,      // [B,N]
           const int*   __restrict__ conn,       // [N,K]
           float*       __restrict__ out)        // [T+1,B,N]
{
    __shared__ __align__(16) float th[2][Nn];             // replicated phases
    __shared__ __align__(8)  unsigned long long mbar[2];  // one per buffer

    uint32_t rank;
    asm("mov.u32 %0, %%cluster_ctarank;" : "=r"(rank));
    const int b   = blockIdx.x / CSZ;
    const int tid = threadIdx.x;
    const int n   = (int)rank * NPC + tid;

    const uint32_t mb_l0 = smem_u32(&mbar[0]);
    const uint32_t mb_l1 = smem_u32(&mbar[1]);
    if (tid == 0) {
        mbar_init(mb_l0, 1);   // 1 arrival (arming thread) + tx bytes
        mbar_init(mb_l1, 1);
    }

    // ---- prologue: dedup couplings, fold eps/n into weights ----
    float w[Kk];
    int   off[Kk];
    int idx[Kk];
    #pragma unroll
    for (int k = 0; k < Kk; ++k) idx[k] = conn[n * Kk + k];

    int cnt = 0;
    #pragma unroll
    for (int k = 0; k < Kk; ++k) {
        bool win = true;
        #pragma unroll
        for (int k2 = k + 1; k2 < Kk; ++k2) win = win && (idx[k2] != idx[k]);
        const float c = coupling[((size_t)b * Nn + n) * Kk + k];
        w[k]   = win ? c : 0.0f;
        off[k] = idx[k];
        cnt += (win && (c != 0.0f)) ? 1 : 0;
    }
    const float inv = (cnt > 0) ? (1.0f / (float)cnt) : 0.0f;
    #pragma unroll
    for (int k = 0; k < Kk; ++k) w[k] *= inv;

    float p  = phase0[(size_t)b * Nn + n];
    const float om = omega[(size_t)b * Nn + n];
    out[(size_t)b * Nn + n] = p;                 // t=0 slice

    // each CTA fills its FULL th[0] locally from gmem (4 per thread)
    #pragma unroll
    for (int j = 0; j < CSZ; ++j) {
        const int m  = tid + j * THREADS;
        const float q = phase0[(size_t)b * Nn + m];
        th[0][m] = q - TWO_PI * rintf(q * INV_TWO_PI);
    }
    float pr = p - TWO_PI * rintf(p * INV_TWO_PI);

    // hoisted push addresses (sender threads tid<3): peer slice dst + peer mbar
    const uint32_t peer = (tid < CSZ - 1)
        ? ((uint32_t)tid < rank ? (uint32_t)tid : (uint32_t)(tid + 1)) : 0u;
    const uint32_t src_l[2] = { smem_u32(&th[0][rank * NPC]),
                                smem_u32(&th[1][rank * NPC]) };
    uint32_t dst_r[2], mbr_r[2];
    if (tid < CSZ - 1) {
        dst_r[0] = mapa_u32(src_l[0], peer);
        dst_r[1] = mapa_u32(src_l[1], peer);
        mbr_r[0] = mapa_u32(mb_l0, peer);
        mbr_r[1] = mapa_u32(mb_l1, peer);
    }

    __syncthreads();   // th[0] + mbarrier init complete at CTA scope
    // cluster-wide: all mbarriers initialized before any peer bulk signals
    asm volatile("barrier.cluster.arrive.aligned;" ::: "memory");
    asm volatile("barrier.cluster.wait.aligned;"   ::: "memory");

    uint32_t par[2] = {0, 0};

    // ---- time stepping ----
    #pragma unroll 1
    for (int t = 0; t < Tt; ++t) {
        const int c  = t & 1;
        const int nb = c ^ 1;

        if (t > 0) {                 // all 6144 remote bytes of buffer c in
            mbar_wait(c ? mb_l1 : mb_l0, par[c]);
            par[c] ^= 1u;
        }

        const float* __restrict__ cur = th[c];

        // explicit prefetch batch: issue all 8 gathers before the MUFU chain
        float pm[Kk];
        #pragma unroll
        for (int k = 0; k < Kk; ++k) pm[k] = cur[off[k]];

        float acc = 0.0f;
        #pragma unroll
        for (int k = 0; k < Kk; ++k)
            acc += w[k] * __sinf(pm[k] - pr);    // arg in [-2pi, 2pi]

        p += acc + om;
        const float prn = p - TWO_PI * rintf(p * INV_TWO_PI);
        pr = prn;

        // own slice into own next buffer
        th[nb][n] = prn;

        if (t < Tt - 1) {
            __syncthreads();         // slice complete before engine reads it
            // send FIRST (critical path), then fill the gap with STG + arming
            if (tid < CSZ - 1) {
                asm volatile("fence.proxy.async.shared::cta;" ::: "memory");
                bulk_s2s_cluster(dst_r[nb], src_l[nb], SLICE_BYTES, mbr_r[nb]);
            }
            out[(size_t)(t + 1) * (Bb * Nn) + (size_t)b * Nn + n] = p;
            if (tid == 0)            // arm for next use; late-arm is legal
                mbar_arrive_expect_tx(nb ? mb_l1 : mb_l0, EXPECT_BYTES);
        } else {
            out[(size_t)(t + 1) * (Bb * Nn) + (size_t)b * Nn + n] = p;
        }
    }
}

extern "C" void kernel_launch(void* const* d_in, const int* in_sizes, int n_in,
                              void* d_out, int out_size)
{
    const float* coupling = (const float*)d_in[0];   // [B,N,K] f32
    const float* phase0   = (const float*)d_in[1];   // [B,N]   f32
    const float* omega    = (const float*)d_in[2];   // [B,N]   f32
    const int*   conn     = (const int*)  d_in[3];   // [N,K]   i32
    float*       out      = (float*)d_out;           // [T+1,B,N] f32

    osc_kernel<<<Bb * CSZ, THREADS>>>(coupling, phase0, omega, conn, out);
}